// round 8
// baseline (speedup 1.0000x reference)
#include <cuda_runtime.h>
#include <cuda_fp16.h>
#include <math.h>
#include <stdint.h>

#define NN 50000
#define EE 800000
#define IN_DIM 128
#define EMB 64
#define HDIM 256
#define RR 12
#define BB 8
#define NGENE 20000
#define NPATH 2000
#define IN1 192
#define NR (NN * RR)

// ---------------- static scratch (fp16 feature planes) ----------------
__device__ __half g_x0h[(size_t)NN * IN1];
__device__ __half g_h1h[(size_t)NN * HDIM];
__device__ __half g_h2h[(size_t)NN * HDIM];
__device__ __half g_aggBh[(size_t)NN * BB * HDIM];
__device__ int    g_cnt[NR];          // zeroed at end of k_scan each run
__device__ int    g_off[NR + 1];
__device__ int    g_wof[NR];
__device__ int    g_esrc[EE];

// ---------------- helpers ----------------
__device__ __forceinline__ void split_pair_h(float a, float b, uint32_t& wh, uint32_t& wl) {
    half2 h = __floats2half2_rn(a, b);
    float2 r = __half22float2(h);
    half2 l = __floats2half2_rn(a - r.x, b - r.y);
    wh = *reinterpret_cast<uint32_t*>(&h);
    wl = *reinterpret_cast<uint32_t*>(&l);
}
__device__ __forceinline__ void mma16h(float* d, const uint32_t* a, const uint32_t* b) {
    asm volatile(
        "mma.sync.aligned.m16n8k16.row.col.f32.f16.f16.f32 "
        "{%0,%1,%2,%3}, {%4,%5,%6,%7}, {%8,%9}, {%0,%1,%2,%3};"
        : "+f"(d[0]), "+f"(d[1]), "+f"(d[2]), "+f"(d[3])
        : "r"(a[0]), "r"(a[1]), "r"(a[2]), "r"(a[3]), "r"(b[0]), "r"(b[1]));
}
#define BSCALE 256.0f
#define INV_BSCALE (1.0f / 256.0f)

// ---------------- 1: build x0 (fp16) + edge counts ----------------
__global__ void k_build_count(const float* __restrict__ x,
                              const int* __restrict__ ei, const int* __restrict__ et) {
    int i = blockIdx.x * blockDim.x + threadIdx.x;
    if (i < EE) atomicAdd(&g_cnt[ei[EE + i] * RR + et[i]], 1);
    if (i >= NN * IN1) return;
    int n = i / IN1, c = i - n * IN1;
    g_x0h[i] = (c < IN_DIM) ? __float2half(x[(size_t)n * IN_DIM + c]) : __half(0.f);
}

// ---------------- 2: single-block scan; re-zero g_cnt ----------------
__global__ void k_scan() {
    __shared__ int bs[1024];
    const int CH = (NR + 1023) / 1024;
    int t = threadIdx.x;
    int base = t * CH;
    int s = 0;
    for (int j = 0; j < CH; j++) {
        int i = base + j;
        if (i < NR) s += g_cnt[i];
    }
    bs[t] = s;
    __syncthreads();
    for (int off = 1; off < 1024; off <<= 1) {
        int v = (t >= off) ? bs[t - off] : 0;
        __syncthreads();
        bs[t] += v;
        __syncthreads();
    }
    int run = (t == 0) ? 0 : bs[t - 1];
    for (int j = 0; j < CH; j++) {
        int i = base + j;
        if (i < NR) {
            int c = g_cnt[i];
            g_off[i] = run;
            g_wof[i] = run;
            g_cnt[i] = 0;
            run += c;
        }
    }
    if (t == 1023) g_off[NR] = run;
}

// ---------------- 3: CSR fill + embedding writes (cols 128.. are pure emb) ----------------
#define FILL_TOT (EE + (NGENE + NPATH) * EMB)
__global__ void k_fill_embs(const int* __restrict__ ei, const int* __restrict__ et,
                            const int* __restrict__ gidx, const int* __restrict__ pidx,
                            const float* __restrict__ gemb, const float* __restrict__ pemb) {
    int i = blockIdx.x * blockDim.x + threadIdx.x;
    if (i < EE) {
        int flat = ei[EE + i] * RR + et[i];
        int p = atomicAdd(&g_wof[flat], 1);
        g_esrc[p] = ei[i];
    } else if (i < EE + NGENE * EMB) {
        int t = i - EE;
        int g = t / EMB, j = t - g * EMB;
        g_x0h[(size_t)gidx[g] * IN1 + IN_DIM + j] = __float2half(gemb[t]);
    } else if (i < FILL_TOT) {
        int t = i - EE - NGENE * EMB;
        int g = t / EMB, j = t - g * EMB;
        g_x0h[(size_t)pidx[g] * IN1 + IN_DIM + j] = __float2half(pemb[t]);
    }
}

// ---------------- 4/6: gather-aggregate (fp16 in/out, fp32 accum) ----------------
// GROUP threads per node, CP = K/GROUP half-columns per thread, NPB nodes per block.
template <int K, int LAYER, int GROUP, int NPB>
__global__ void __launch_bounds__(GROUP* NPB)
k_agg(const float* __restrict__ comp) {
    constexpr int CP = K / GROUP;   // 4 (L1) or 8 (L2)
    __shared__ float sc[RR * BB];
    const int tid = threadIdx.x;
    for (int i = tid; i < RR * BB; i += GROUP * NPB) sc[i] = comp[i];
    __syncthreads();

    const int g    = tid / GROUP;
    const int lane = tid % GROUP;
    const int n    = blockIdx.x * NPB + g;
    const __half* __restrict__ xin = (LAYER == 1) ? g_x0h : g_h1h;

    float acc[BB][CP];
#pragma unroll
    for (int b = 0; b < BB; b++)
#pragma unroll
        for (int c = 0; c < CP; c++) acc[b][c] = 0.f;

    int off0 = g_off[n * RR];
#pragma unroll
    for (int r = 0; r < RR; r++) {
        int off1 = g_off[n * RR + r + 1];
        int cnt = off1 - off0;
        if (cnt > 0) {
            float s[CP];
#pragma unroll
            for (int c = 0; c < CP; c++) s[c] = 0.f;
            for (int j = off0; j < off1; j++) {
                int src = __ldg(&g_esrc[j]);
                const __half* p = xin + (size_t)src * K + lane * CP;
                if (CP == 4) {
                    uint2 u = *reinterpret_cast<const uint2*>(p);
                    float2 f0 = __half22float2(*reinterpret_cast<half2*>(&u.x));
                    float2 f1 = __half22float2(*reinterpret_cast<half2*>(&u.y));
                    s[0] += f0.x; s[1] += f0.y; s[2] += f1.x; s[3] += f1.y;
                } else {
                    uint4 u = *reinterpret_cast<const uint4*>(p);
                    float2 f0 = __half22float2(*reinterpret_cast<half2*>(&u.x));
                    float2 f1 = __half22float2(*reinterpret_cast<half2*>(&u.y));
                    float2 f2 = __half22float2(*reinterpret_cast<half2*>(&u.z));
                    float2 f3 = __half22float2(*reinterpret_cast<half2*>(&u.w));
                    s[0] += f0.x; s[1] += f0.y; s[2] += f1.x; s[3] += f1.y;
                    s[4 % CP] += f2.x; s[5 % CP] += f2.y; s[6 % CP] += f3.x; s[7 % CP] += f3.y;
                }
            }
            float inv = 1.f / (float)cnt;
#pragma unroll
            for (int b = 0; b < BB; b++) {
                float w = sc[r * BB + b] * inv;
#pragma unroll
                for (int c = 0; c < CP; c++) acc[b][c] = fmaf(w, s[c], acc[b][c]);
            }
        }
        off0 = off1;
    }

    __half* dst = g_aggBh + (size_t)n * (BB * K) + lane * CP;
#pragma unroll
    for (int b = 0; b < BB; b++) {
        if (CP == 4) {
            half2 h0 = __floats2half2_rn(acc[b][0], acc[b][1]);
            half2 h1 = __floats2half2_rn(acc[b][2], acc[b][3]);
            uint2 u = make_uint2(*reinterpret_cast<uint32_t*>(&h0), *reinterpret_cast<uint32_t*>(&h1));
            *reinterpret_cast<uint2*>(dst + b * K) = u;
        } else {
            half2 h0 = __floats2half2_rn(acc[b][0], acc[b][1]);
            half2 h1 = __floats2half2_rn(acc[b][2], acc[b][3]);
            half2 h2 = __floats2half2_rn(acc[b][4 % CP], acc[b][5 % CP]);
            half2 h3 = __floats2half2_rn(acc[b][6 % CP], acc[b][7 % CP]);
            uint4 u = make_uint4(*reinterpret_cast<uint32_t*>(&h0), *reinterpret_cast<uint32_t*>(&h1),
                                 *reinterpret_cast<uint32_t*>(&h2), *reinterpret_cast<uint32_t*>(&h3));
            *reinterpret_cast<uint4*>(dst + b * K) = u;
        }
    }
}

// ---------------- 5/7: GEMM 2-term FP16, 512 threads / 16 warps (4/SMSP) ----------------
// CTA 128 rows x 256 cols, warps 4m x 4n (tile 32x64), BK=16, double-buffered smem.
// word layout: A[2st][128][12] = 3072 | B[2st][hi/lo][8][264] = 8448 (@3072) |
// bias@11520 att@11776 sc@12032(512) al@12544(512) -> 13056 words
#define GEMM_SMEM_BYTES (13056 * 4)

template <int KIN, int LAYER>
__global__ void __launch_bounds__(512, 1)
k_gemm(const float* __restrict__ basis, const float* __restrict__ root,
       const float* __restrict__ bias,  const float* __restrict__ att) {
    constexpr int KB   = BB * KIN;
    constexpr int KTOT = 9 * KIN;
    constexpr int T    = KTOT / 16;

    extern __shared__ float sm[];
    uint32_t* smw = reinterpret_cast<uint32_t*>(sm);
    float* s_bias = sm + 11520;
    float* s_att  = sm + 11776;
    float* s_sc   = sm + 12032;
    float* s_al   = sm + 12544;

    const int tid  = threadIdx.x;
    const int lane = tid & 31;
    const int wid  = tid >> 5;     // 0..15
    const int wm   = wid >> 2;     // 0..3
    const int wn   = wid & 3;      // 0..3 (head)
    const int m0   = blockIdx.x * 128;

    const __half* __restrict__ xinh = (LAYER == 1) ? g_x0h : g_h1h;
    __half*       houth             = (LAYER == 1) ? g_h1h : g_h2h;

    if (tid < 256) { s_bias[tid] = bias[tid]; s_att[tid] = att[tid]; }

    float acc[2][8][4];
#pragma unroll
    for (int a = 0; a < 2; a++)
#pragma unroll
        for (int b = 0; b < 8; b++)
#pragma unroll
            for (int c = 0; c < 4; c++) acc[a][b][c] = 0.f;

    uint2  aReg;
    float4 bReg[2];
    const int am = tid >> 2, ak4 = (tid & 3) << 2;     // A: 128 rows x 4 halfs
    const int bkp = tid >> 6, bn4 = (tid & 63) << 2;   // B: 8 k-pairs x 4 cols

    auto gload = [&](int t) {
        int k0 = t * 16;
        int row = m0 + am;
        int kc = k0 + ak4;
        if (row < NN) {
            const __half* src = (kc < KB) ? (g_aggBh + (size_t)row * KB + kc)
                                          : (xinh + (size_t)row * KIN + (kc - KB));
            aReg = *reinterpret_cast<const uint2*>(src);
        } else {
            aReg = make_uint2(0u, 0u);
        }
        int kk = k0 + 2 * bkp;
        const float* s0 = (kk < KB) ? (basis + (size_t)kk * 256 + bn4)
                                    : (root + (size_t)(kk - KB) * 256 + bn4);
        bReg[0] = *reinterpret_cast<const float4*>(s0);
        bReg[1] = *reinterpret_cast<const float4*>(s0 + 256);
    };
    auto sstore = [&](int t) {
        int s = t & 1;
        *reinterpret_cast<uint2*>(smw + s * 1536 + am * 12 + (ak4 >> 1)) = aReg;
        uint32_t* Bh = smw + 3072 + s * 4224;
        uint32_t* Bl = Bh + 2112;
        uint32_t h[4], l[4];
        split_pair_h(bReg[0].x * BSCALE, bReg[1].x * BSCALE, h[0], l[0]);
        split_pair_h(bReg[0].y * BSCALE, bReg[1].y * BSCALE, h[1], l[1]);
        split_pair_h(bReg[0].z * BSCALE, bReg[1].z * BSCALE, h[2], l[2]);
        split_pair_h(bReg[0].w * BSCALE, bReg[1].w * BSCALE, h[3], l[3]);
        int w = bkp * 264 + bn4;
        *reinterpret_cast<uint4*>(Bh + w) = make_uint4(h[0], h[1], h[2], h[3]);
        *reinterpret_cast<uint4*>(Bl + w) = make_uint4(l[0], l[1], l[2], l[3]);
    };

    gload(0);
    sstore(0);
    if (T > 1) gload(1);
    __syncthreads();

    for (int t = 0; t < T; t++) {
        const uint32_t* Ah = smw + (t & 1) * 1536;
        const uint32_t* Bh = smw + 3072 + (t & 1) * 4224;
        const int c = lane & 3;

        uint32_t ah[2][4];
#pragma unroll
        for (int mi = 0; mi < 2; mi++) {
            int r0 = wm * 32 + mi * 16 + (lane >> 2);
            int i0 = r0 * 12 + c;
            int i1 = (r0 + 8) * 12 + c;
            ah[mi][0] = Ah[i0];     ah[mi][1] = Ah[i1];
            ah[mi][2] = Ah[i0 + 4]; ah[mi][3] = Ah[i1 + 4];
        }
        // phase hi (16-MMA accumulator reuse distance)
#pragma unroll
        for (int ni = 0; ni < 8; ni++) {
            int n = wn * 64 + ni * 8 + (lane >> 2);
            uint32_t b0[2] = {Bh[c * 264 + n], Bh[(c + 4) * 264 + n]};
            mma16h(acc[0][ni], ah[0], b0);
            mma16h(acc[1][ni], ah[1], b0);
        }
        // phase lo
#pragma unroll
        for (int ni = 0; ni < 8; ni++) {
            int n = wn * 64 + ni * 8 + (lane >> 2);
            uint32_t b1[2] = {Bh[2112 + c * 264 + n], Bh[2112 + (c + 4) * 264 + n]};
            mma16h(acc[0][ni], ah[0], b1);
            mma16h(acc[1][ni], ah[1], b1);
        }

        if (t + 1 < T) sstore(t + 1);
        if (t + 2 < T) gload(t + 2);
        __syncthreads();
    }

    // ---- unscale + bias + head scores (warp tile == one full head) ----
    float scv[4] = {0.f, 0.f, 0.f, 0.f};
#pragma unroll
    for (int mi = 0; mi < 2; ++mi)
#pragma unroll
        for (int ni = 0; ni < 8; ++ni) {
            int colb = wn * 64 + ni * 8 + (lane & 3) * 2;
#pragma unroll
            for (int r = 0; r < 4; ++r) {
                int col = colb + (r & 1);
                acc[mi][ni][r] = fmaf(acc[mi][ni][r], INV_BSCALE, s_bias[col]);
                scv[mi * 2 + (r >> 1)] = fmaf(acc[mi][ni][r], s_att[col], scv[mi * 2 + (r >> 1)]);
            }
        }
#pragma unroll
    for (int i = 0; i < 4; ++i) {
        scv[i] += __shfl_xor_sync(0xffffffffu, scv[i], 1);
        scv[i] += __shfl_xor_sync(0xffffffffu, scv[i], 2);
    }
    if ((lane & 3) == 0) {
#pragma unroll
        for (int mi = 0; mi < 2; ++mi) {
            int r0 = wm * 32 + mi * 16 + (lane >> 2);
            s_sc[r0 * 4 + wn]       = scv[mi * 2];
            s_sc[(r0 + 8) * 4 + wn] = scv[mi * 2 + 1];
        }
    }
    __syncthreads();
    if (tid < 128) {
        float v0 = s_sc[tid * 4], v1 = s_sc[tid * 4 + 1];
        float v2 = s_sc[tid * 4 + 2], v3 = s_sc[tid * 4 + 3];
        float mx = fmaxf(fmaxf(v0, v1), fmaxf(v2, v3));
        float e0 = expf(v0 - mx), e1 = expf(v1 - mx), e2 = expf(v2 - mx), e3 = expf(v3 - mx);
        float inv = 1.f / (e0 + e1 + e2 + e3);
        s_al[tid * 4]     = e0 * inv;
        s_al[tid * 4 + 1] = e1 * inv;
        s_al[tid * 4 + 2] = e2 * inv;
        s_al[tid * 4 + 3] = e3 * inv;
    }
    __syncthreads();

    // ---- scaled fp16 store ----
#pragma unroll
    for (int mi = 0; mi < 2; ++mi) {
        int lr0 = wm * 32 + mi * 16 + (lane >> 2);
        int rowA = m0 + lr0, rowB = rowA + 8;
        float aA = s_al[lr0 * 4 + wn];
        float aB = s_al[(lr0 + 8) * 4 + wn];
#pragma unroll
        for (int ni = 0; ni < 8; ++ni) {
            int col = wn * 64 + ni * 8 + (lane & 3) * 2;
            if (rowA < NN) {
                half2 o = __floats2half2_rn(acc[mi][ni][0] * aA, acc[mi][ni][1] * aA);
                *reinterpret_cast<half2*>(houth + (size_t)rowA * HDIM + col) = o;
            }
            if (rowB < NN) {
                half2 o = __floats2half2_rn(acc[mi][ni][2] * aB, acc[mi][ni][3] * aB);
                *reinterpret_cast<half2*>(houth + (size_t)rowB * HDIM + col) = o;
            }
        }
    }
}

// ---------------- 8: final prediction (reads fp16 h2) ----------------
__global__ void k_pred(const float* __restrict__ pw, const float* __restrict__ pb,
                       float* __restrict__ out) {
    __shared__ float wt[12 * HDIM];
    int tid = threadIdx.x;
    for (int i = tid; i < HDIM * 12; i += blockDim.x) {
        int c = i / 12, j = i - c * 12;
        wt[j * HDIM + c] = pw[i];
    }
    __syncthreads();
    int warp = tid >> 5, lane = tid & 31;
    int n = blockIdx.x * 8 + warp;
    if (n >= NN) return;
    float acc[12];
#pragma unroll
    for (int j = 0; j < 12; j++) acc[j] = 0.f;
#pragma unroll
    for (int c0 = 0; c0 < 8; c0++) {
        int c = c0 * 32 + lane;
        float v = __half2float(g_h2h[(size_t)n * HDIM + c]);
#pragma unroll
        for (int j = 0; j < 12; j++) acc[j] = fmaf(v, wt[j * HDIM + c], acc[j]);
    }
#pragma unroll
    for (int j = 0; j < 12; j++) {
#pragma unroll
        for (int off = 16; off; off >>= 1)
            acc[j] += __shfl_xor_sync(0xffffffffu, acc[j], off);
    }
    if (lane == 0) {
#pragma unroll
        for (int j = 0; j < 12; j++) out[(size_t)n * 12 + j] = acc[j] + pb[j];
    }
}

// ---------------- launch ----------------
extern "C" void kernel_launch(void* const* d_in, const int* in_sizes, int n_in,
                              void* d_out, int out_size) {
    const float* x      = (const float*)d_in[0];
    const int*   ei     = (const int*)d_in[1];
    const int*   et     = (const int*)d_in[2];
    const int*   gidx   = (const int*)d_in[3];
    const int*   pidx   = (const int*)d_in[4];
    const float* gemb   = (const float*)d_in[5];
    const float* pemb   = (const float*)d_in[6];
    const float* comp1  = (const float*)d_in[7];
    const float* basis1 = (const float*)d_in[8];
    const float* root1  = (const float*)d_in[9];
    const float* bias1  = (const float*)d_in[10];
    const float* att1   = (const float*)d_in[11];
    const float* comp2  = (const float*)d_in[12];
    const float* basis2 = (const float*)d_in[13];
    const float* root2  = (const float*)d_in[14];
    const float* bias2  = (const float*)d_in[15];
    const float* att2   = (const float*)d_in[16];
    const float* predw  = (const float*)d_in[17];
    const float* predb  = (const float*)d_in[18];
    float* out = (float*)d_out;

    const int TPB = 256;

    cudaFuncSetAttribute(k_gemm<IN1, 1>,  cudaFuncAttributeMaxDynamicSharedMemorySize, GEMM_SMEM_BYTES);
    cudaFuncSetAttribute(k_gemm<HDIM, 2>, cudaFuncAttributeMaxDynamicSharedMemorySize, GEMM_SMEM_BYTES);

    // 1: x0(fp16) + counts
    k_build_count<<<(NN * IN1 + TPB - 1) / TPB, TPB>>>(x, ei, et);
    // 2: scan -> offsets (+ re-zero g_cnt)
    k_scan<<<1, 1024>>>();
    // 3: CSR fill + embeddings
    k_fill_embs<<<(FILL_TOT + TPB - 1) / TPB, TPB>>>(ei, et, gidx, pidx, gemb, pemb);
    // 4: aggregate layer 1 (profiled slot): 4 nodes x 48 threads
    k_agg<IN1, 1, 48, 4><<<NN / 4, 192>>>(comp1);
    // 5: GEMM layer 1
    k_gemm<IN1, 1><<<(NN + 127) / 128, 512, GEMM_SMEM_BYTES>>>(basis1, root1, bias1, att1);
    // 6: aggregate layer 2: 8 nodes x 32 threads
    k_agg<HDIM, 2, 32, 8><<<NN / 8, 256>>>(comp2);
    // 7: GEMM layer 2
    k_gemm<HDIM, 2><<<(NN + 127) / 128, 512, GEMM_SMEM_BYTES>>>(basis2, root2, bias2, att2);
    // 8: prediction head
    k_pred<<<(NN + 7) / 8, TPB>>>(predw, predb, out);
}